// round 10
// baseline (speedup 1.0000x reference)
#include <cuda_runtime.h>

#define HH 1024
#define WW 1024
#define NC 128
#define NITER 8
#define NREP 16        // global accumulator replicas
#define NBLKP 128      // persistent blocks (all resident: 128 <= 148 SMs)
#define TPB 1024
#define TPBLK 8        // 32x32 tiles per block (8 horizontally adjacent)
#define REPS 8         // shared accumulator replicas (one per 4 warps)

// Global state (zero-initialized at module load; kernel leaves g_arrive==0
// and treats g_gen as monotonic across launches via an entry snapshot).
__device__ float2   g_part[NITER][NREP][NC];
__device__ float2   g_cl[NC];
__device__ int      g_cli[NC];
__device__ int      g_ncl;
__device__ unsigned g_gen;
__device__ int      g_arrive;

__device__ __forceinline__ unsigned coord_hash(float2 c)
{
    unsigned hx = __float_as_uint(c.x), hy = __float_as_uint(c.y);
    unsigned h = hx * 2654435761u ^ hy * 40503u;
    return (h ^ (h >> 16)) & 255u;
}

__device__ __forceinline__ void bar_arrive()
{
    __syncthreads();
    if (threadIdx.x == 0) { __threadfence(); atomicAdd(&g_arrive, 1); }
}

__device__ __forceinline__ void bar_wait_gen(unsigned base, unsigned k)
{
    if (threadIdx.x == 0) {
        while (*(volatile unsigned*)&g_gen - base < k) __nanosleep(64);
    }
    __syncthreads();
    __threadfence();
}

__device__ __forceinline__ void bar0_wait_all()
{
    if (threadIdx.x == 0) {
        while (*(volatile int*)&g_arrive < NBLKP) __nanosleep(32);
    }
    __syncthreads();
    __threadfence();
}

__device__ __forceinline__ void bar0_release()
{
    __syncthreads();
    if (threadIdx.x == 0) {
        *(volatile int*)&g_arrive = 0;   // safe: nobody touches until after gen bump
        __threadfence();
        atomicAdd(&g_gen, 1);
    }
}

__global__ __launch_bounds__(TPB, 1)
void kmeans_persist(const float* __restrict__ clusters,
                    const float* __restrict__ heat,
                    float2* __restrict__ out)
{
    __shared__ float2   s_scl[TPBLK][NC];
    __shared__ int      s_sidx[TPBLK][NC];
    __shared__ float2   s_acc[REPS][NC];
    __shared__ float    s_wm[TPBLK][4];
    __shared__ int      s_wc[TPBLK][4];
    __shared__ int      s_ns[TPBLK];
    __shared__ int      s_hslot[256];
    __shared__ float2   s_tmp[NC];
    __shared__ unsigned s_base;

    const int tid  = threadIdx.x;
    const int bid  = blockIdx.x;
    const int wid  = tid >> 5;
    const int lane = tid & 31;
    const unsigned full = 0xffffffffu;

    if (tid == 0) s_base = *(volatile unsigned*)&g_gen;  // before our arrival

    // Tile geometry: linear tile tl = bid*8 + t; tr = tl>>5 (same for all 8
    // tiles of a block since bid*8 % 32 in {0,8,16,24}), tc = tl & 31.
    const int tl0  = bid * TPBLK;
    const int tr   = tl0 >> 5;
    const int pr   = tid >> 5;           // row within tile (== wid)
    const int pc   = tid & 31;           // col within tile
    const int grow = tr * 32 + pr;
    const float fi = (float)grow;

    // ---- heatmap -> registers, once for the whole run ----
    float h[TPBLK];
    #pragma unroll
    for (int t = 0; t < TPBLK; ++t) {
        int gcol = ((tl0 + t) & 31) * 32 + pc;
        h[t] = heat[grow * WW + gcol];
    }

    // ---- zero the global replica accumulators (first 32 blocks) ----
    {
        int gi = bid * TPB + tid;
        if (gi < NITER * NREP * NC * 2) ((float*)g_part)[gi] = 0.f;
    }
    __syncthreads();                       // also publishes s_base
    const unsigned base = s_base;

    // ============ barrier 0: block 0 builds initial candidate list ============
    bar_arrive();
    if (bid == 0) {
        bar0_wait_all();
        if (tid < 256) s_hslot[tid] = 1 << 30;
        if (tid < NC)  s_tmp[tid] = ((const float2*)clusters)[tid];
        __syncthreads();
        float2 cs = make_float2(0.f, 0.f); unsigned hsh = 0;
        if (tid < NC) { cs = s_tmp[tid]; hsh = coord_hash(cs); atomicMin(&s_hslot[hsh], tid); }
        __syncthreads();
        // Hash dedup (exact for the strict-< argmin tie-break; a collision can
        // only MISS a dedup, which is harmless since survivors stay index-sorted).
        bool uniq = false;
        if (tid < NC) {
            uniq = true;
            int w = s_hslot[hsh];
            if (w < tid) { float2 o = s_tmp[w]; uniq = !((o.x == cs.x) & (o.y == cs.y)); }
        }
        unsigned bal = __ballot_sync(full, uniq);
        if (lane == 0 && tid < NC) s_wc[0][wid] = __popc(bal);
        __syncthreads();
        if (tid < NC) {
            int b = (wid > 0 ? s_wc[0][0] : 0) + (wid > 1 ? s_wc[0][1] : 0) + (wid > 2 ? s_wc[0][2] : 0);
            if (uniq) {
                int pos = b + __popc(bal & ((1u << lane) - 1u));
                g_cl[pos] = cs; g_cli[pos] = tid;   // ascending index preserved
            }
        }
        if (tid == 0) g_ncl = s_wc[0][0] + s_wc[0][1] + s_wc[0][2] + s_wc[0][3];
        bar0_release();
    } else {
        bar_wait_gen(base, 1);
    }

    // ============================== iterations ==============================
    for (int it = 0; it < NITER; ++it) {
        const int ncl = g_ncl;

        // ---- fused preamble: thread = (tile ts = tid>>7, candidate c = tid&127)
        const int ts = tid >> 7;
        const int c  = tid & 127;
        float  cd2 = 3.4e38f;
        float2 cl  = make_float2(0.f, 0.f);
        int    cidx = 0;
        if (c < ncl) {
            cl = g_cl[c]; cidx = g_cli[c];
            float cy = (float)(tr * 32) + 15.5f;
            float cx = (float)(((tl0 + ts) & 31) * 32) + 15.5f;
            float dr = cy - cl.x, dc = cx - cl.y;
            cd2 = __fadd_rn(__fmul_rn(dr, dr), __fmul_rn(dc, dc));
        }
        float m = cd2;
        #pragma unroll
        for (int o = 16; o; o >>= 1) m = fminf(m, __shfl_xor_sync(full, m, o));
        if (lane == 0) s_wm[ts][wid & 3] = m;
        ((float2*)s_acc)[tid] = make_float2(0.f, 0.f);     // zero smem replicas
        __syncthreads();

        float mind2 = fminf(fminf(s_wm[ts][0], s_wm[ts][1]),
                            fminf(s_wm[ts][2], s_wm[ts][3]));
        // keep c iff dist(center,c) <= min + 2r (+margin); r=15.5*sqrt2, 2r=43.84
        float thr = sqrtf(mind2) + 44.9f;
        bool pred = (c < ncl) && (cd2 <= thr * thr);
        unsigned bal = __ballot_sync(full, pred);
        if (lane == 0) s_wc[ts][wid & 3] = __popc(bal);
        __syncthreads();

        {
            int wig = wid & 3;
            int b = (wig > 0 ? s_wc[ts][0] : 0) + (wig > 1 ? s_wc[ts][1] : 0) + (wig > 2 ? s_wc[ts][2] : 0);
            if (pred) {
                int pos = b + __popc(bal & ((1u << lane) - 1u));
                s_scl[ts][pos]  = cl;
                s_sidx[ts][pos] = cidx;     // ascending original index
            }
            if (c == 0) s_ns[ts] = s_wc[ts][0] + s_wc[ts][1] + s_wc[ts][2] + s_wc[ts][3];
        }
        __syncthreads();

        // ---- pixel pass: 8 tiles, register accumulation per current winner ----
        int   curidx = -1;
        float ax = 0.f, ay = 0.f;
        const int rep = wid & (REPS - 1);
        #pragma unroll
        for (int t = 0; t < TPBLK; ++t) {
            const int   ns = s_ns[t];
            const float fj = (float)(((tl0 + t) & 31) * 32 + pc);
            float best = 3.4e38f; int bs = 0;
            for (int s = 0; s < ns; ++s) {
                float2 cc = s_scl[t][s];
                float dr = fi - cc.x, dc = fj - cc.y;
                // match reference: dr*dr + dc*dc (no fma), clamp >= 1
                float d2 = fmaxf(__fadd_rn(__fmul_rn(dr, dr), __fmul_rn(dc, dc)), 1.0f);
                if (d2 < best) { best = d2; bs = s; }
            }
            float w = h[t] * __frsqrt_rn(best);
            int ci = s_sidx[t][bs];
            if (ci != curidx) {
                if (curidx >= 0) {
                    atomicAdd(&s_acc[rep][curidx].x, ax);
                    atomicAdd(&s_acc[rep][curidx].y, ay);
                }
                curidx = ci; ax = 0.f; ay = 0.f;
            }
            ax = __fmaf_rn(fi, w, ax);
            ay = __fmaf_rn(fj, w, ay);
        }
        // final flush: warp-uniform fast path
        int  sref = __shfl_sync(full, curidx, 0);
        bool uni  = __all_sync(full, curidx == sref);
        if (uni) {
            #pragma unroll
            for (int o = 16; o; o >>= 1) {
                ax += __shfl_xor_sync(full, ax, o);
                ay += __shfl_xor_sync(full, ay, o);
            }
            if (lane == 0) {
                atomicAdd(&s_acc[rep][sref].x, ax);
                atomicAdd(&s_acc[rep][sref].y, ay);
            }
        } else {
            atomicAdd(&s_acc[rep][curidx].x, ax);
            atomicAdd(&s_acc[rep][curidx].y, ay);
        }
        __syncthreads();

        // ---- flush nonzero cluster partials to this block's global replica ----
        if (tid < NC) {
            float x = 0.f, y = 0.f;
            #pragma unroll
            for (int r = 0; r < REPS; ++r) { x += s_acc[r][tid].x; y += s_acc[r][tid].y; }
            float2* dst = g_part[it][bid & (NREP - 1)];
            if (x != 0.f) atomicAdd(&dst[tid].x, x);
            if (y != 0.f) atomicAdd(&dst[tid].y, y);
        }

        // ---- grid barrier; coordinator rebuilds candidates / writes output ----
        bar_arrive();
        if (bid == 0) {
            bar0_wait_all();
            if (tid < 256) s_hslot[tid] = 1 << 30;
            if (tid < NC) {
                float x = 0.f, y = 0.f;
                #pragma unroll
                for (int r = 0; r < NREP; ++r) {
                    float2 v = g_part[it][r][tid];
                    x += v.x; y += v.y;
                }
                if (it == NITER - 1) out[tid] = make_float2(x, y);
                else                 s_tmp[tid] = make_float2(x, y);
            }
            if (it < NITER - 1) {
                __syncthreads();
                float2 cs = make_float2(0.f, 0.f); unsigned hsh = 0;
                if (tid < NC) { cs = s_tmp[tid]; hsh = coord_hash(cs); atomicMin(&s_hslot[hsh], tid); }
                __syncthreads();
                bool uniq = false;
                if (tid < NC) {
                    uniq = true;
                    int w = s_hslot[hsh];
                    if (w < tid) { float2 o = s_tmp[w]; uniq = !((o.x == cs.x) & (o.y == cs.y)); }
                }
                unsigned b2 = __ballot_sync(full, uniq);
                if (lane == 0 && tid < NC) s_wc[0][wid] = __popc(b2);
                __syncthreads();
                if (tid < NC) {
                    int b = (wid > 0 ? s_wc[0][0] : 0) + (wid > 1 ? s_wc[0][1] : 0) + (wid > 2 ? s_wc[0][2] : 0);
                    if (uniq) {
                        int pos = b + __popc(b2 & ((1u << lane) - 1u));
                        g_cl[pos] = cs; g_cli[pos] = tid;
                    }
                }
                if (tid == 0) g_ncl = s_wc[0][0] + s_wc[0][1] + s_wc[0][2] + s_wc[0][3];
            }
            bar0_release();
        } else {
            if (it < NITER - 1) bar_wait_gen(base, (unsigned)(it + 2));
            // last iteration: non-coordinator blocks exit without waiting
        }
    }
}

extern "C" void kernel_launch(void* const* d_in, const int* in_sizes, int n_in,
                              void* d_out, int out_size)
{
    // Identify inputs by size: clusters = 256 elems, heatmap = 1M.
    const float* clusters = (const float*)d_in[0];
    const float* heat     = (const float*)d_in[1];
    if (in_sizes[0] != NC * 2) {
        clusters = (const float*)d_in[1];
        heat     = (const float*)d_in[0];
    }
    kmeans_persist<<<NBLKP, TPB>>>(clusters, heat, (float2*)d_out);
}

// round 12
// speedup vs baseline: 1.1148x; 1.1148x over previous
#include <cuda_runtime.h>

#define HH 1024
#define WW 1024
#define NC 128
#define NITER 8
#define NBLKP 128      // persistent blocks, all resident (128 <= 148 SMs)
#define TPB 1024
#define TPBLK 8        // 32x32 tiles per block (8 horizontally adjacent)
#define REPS 8         // shared accumulator replicas (one per 4 warps)

// Cross-block state. g_part2 is double-buffered per-iteration partials,
// fully rewritten each use (no zeroing needed). g_gen is monotonic across
// launches (entry snapshot); g_arrive is left at 0 by the last arriver.
__device__ float2   g_part2[2][NBLKP][NC];
__device__ unsigned g_gen;
__device__ unsigned g_arrive;

__device__ __forceinline__ unsigned coord_hash(float2 c)
{
    unsigned hx = __float_as_uint(c.x), hy = __float_as_uint(c.y);
    unsigned h = hx * 2654435761u ^ hy * 40503u;
    return (h ^ (h >> 16)) & 255u;
}

__global__ __launch_bounds__(TPB, 1)
void kmeans_persist(const float* __restrict__ clusters,
                    const float* __restrict__ heat,
                    float2* __restrict__ out)
{
    __shared__ float2   s_scl[TPBLK][NC];
    __shared__ int      s_sidx[TPBLK][NC];
    __shared__ float2   s_acc[REPS][NC];
    __shared__ float2   s_red[8][NC];
    __shared__ float2   s_tmp[NC];
    __shared__ float2   s_cand[NC];
    __shared__ int      s_ci[NC];
    __shared__ int      s_hslot[256];
    __shared__ float    s_wm[TPBLK][4];
    __shared__ int      s_wc[TPBLK][4];
    __shared__ int      s_ns[TPBLK];
    __shared__ int      s_ncand;
    __shared__ unsigned s_base;

    const int tid  = threadIdx.x;
    const int bid  = blockIdx.x;
    const int wid  = tid >> 5;
    const int lane = tid & 31;
    const unsigned full = 0xffffffffu;

    // generation snapshot BEFORE our first arrival (gen cannot bump until all
    // 128 blocks arrive, and we arrive only after this read -> race-free)
    if (tid == 0) s_base = *(volatile unsigned*)&g_gen;

    // Tile geometry: linear tile tl = bid*8 + t; row tr = tl>>5 is the same
    // for all 8 tiles of a block; warp = pixel row, lane = pixel col.
    const int tl0  = bid * TPBLK;
    const int tr   = tl0 >> 5;
    const int grow = tr * 32 + wid;
    const float fi = (float)grow;

    // ---- heatmap -> registers, once for the whole run ----
    float h[TPBLK];
    #pragma unroll
    for (int t = 0; t < TPBLK; ++t)
        h[t] = heat[grow * WW + ((tl0 + t) & 31) * 32 + lane];

    __syncthreads();                   // publishes s_base
    const unsigned base = s_base;

    for (int it = 0; it < NITER; ++it) {
        // ================= candidate build (every block, in parallel) =======
        const int cc = tid & 127;      // cluster id
        const int rg = tid >> 7;       // row group 0..7
        if (it == 0) {
            if (tid < NC) s_tmp[tid] = ((const float2*)clusters)[tid];
        } else {
            const int p = (it - 1) & 1;
            float sx = 0.f, sy = 0.f;
            #pragma unroll
            for (int r = 0; r < 16; ++r) {       // rows rg, rg+8, ..., rg+120
                float2 v = g_part2[p][rg + r * 8][cc];
                sx += v.x; sy += v.y;
            }
            s_red[rg][cc] = make_float2(sx, sy);
        }
        if (tid < 256) s_hslot[tid] = 1 << 30;
        __syncthreads();

        if (it > 0 && tid < NC) {
            float x = 0.f, y = 0.f;
            #pragma unroll
            for (int r = 0; r < 8; ++r) { x += s_red[r][tid].x; y += s_red[r][tid].y; }
            s_tmp[tid] = make_float2(x, y);
        }
        __syncthreads();

        float2   cs  = make_float2(0.f, 0.f);
        unsigned hsh = 0;
        if (tid < NC) { cs = s_tmp[tid]; hsh = coord_hash(cs); atomicMin(&s_hslot[hsh], tid); }
        __syncthreads();

        // Hash dedup: identical coords at a LOWER index can never win the
        // strict-< argmin -> drop (exact). A collision only MISSES a dedup,
        // which is harmless: survivors remain index-sorted.
        bool uniq = false;
        if (tid < NC) {
            uniq = true;
            int w = s_hslot[hsh];
            if (w < tid) { float2 o = s_tmp[w]; uniq = !((o.x == cs.x) & (o.y == cs.y)); }
        }
        unsigned bal = __ballot_sync(full, uniq);
        if (lane == 0 && tid < NC) s_wc[0][wid] = __popc(bal);
        __syncthreads();
        if (tid < NC) {
            int b = (wid > 0 ? s_wc[0][0] : 0) + (wid > 1 ? s_wc[0][1] : 0) + (wid > 2 ? s_wc[0][2] : 0);
            if (uniq) {
                int pos = b + __popc(bal & ((1u << lane) - 1u));
                s_cand[pos] = cs; s_ci[pos] = tid;    // ascending original index
            }
            if (tid == 0) s_ncand = s_wc[0][0] + s_wc[0][1] + s_wc[0][2] + s_wc[0][3];
        }
        __syncthreads();

        // ================= per-tile pruning preamble ========================
        const int ncand = s_ncand;
        const int ts = tid >> 7;       // tile slot 0..7
        float  cd2 = 3.4e38f;
        float2 cl  = make_float2(0.f, 0.f);
        int    cidx = 0;
        if (cc < ncand) {
            cl = s_cand[cc]; cidx = s_ci[cc];
            float cy = (float)(tr * 32) + 15.5f;
            float cx = (float)(((tl0 + ts) & 31) * 32) + 15.5f;
            float dr = cy - cl.x, dc = cx - cl.y;
            cd2 = __fadd_rn(__fmul_rn(dr, dr), __fmul_rn(dc, dc));
        }
        float m = cd2;
        #pragma unroll
        for (int o = 16; o; o >>= 1) m = fminf(m, __shfl_xor_sync(full, m, o));
        if (lane == 0) s_wm[ts][wid & 3] = m;
        ((float2*)s_acc)[tid] = make_float2(0.f, 0.f);   // zero smem replicas
        __syncthreads();

        float mind2 = fminf(fminf(s_wm[ts][0], s_wm[ts][1]),
                            fminf(s_wm[ts][2], s_wm[ts][3]));
        // keep c iff dist(center,c) <= min + 2r (+margin); r=15.5*sqrt2, 2r=43.84
        float thr = sqrtf(mind2) + 44.9f;
        bool pred = (cc < ncand) && (cd2 <= thr * thr);
        unsigned pb = __ballot_sync(full, pred);
        if (lane == 0) s_wc[ts][wid & 3] = __popc(pb);
        __syncthreads();
        {
            int wig = wid & 3;
            int b = (wig > 0 ? s_wc[ts][0] : 0) + (wig > 1 ? s_wc[ts][1] : 0) + (wig > 2 ? s_wc[ts][2] : 0);
            if (pred) {
                int pos = b + __popc(pb & ((1u << lane) - 1u));
                s_scl[ts][pos]  = cl;
                s_sidx[ts][pos] = cidx;      // ascending original index
            }
            if (cc == 0) s_ns[ts] = s_wc[ts][0] + s_wc[ts][1] + s_wc[ts][2] + s_wc[ts][3];
        }
        __syncthreads();

        // ================= pixel pass (register accumulation) ===============
        int   curidx = -1;
        float ax = 0.f, ay = 0.f;
        const int rep = wid & (REPS - 1);
        #pragma unroll
        for (int t = 0; t < TPBLK; ++t) {
            const int   ns = s_ns[t];
            const float fj = (float)(((tl0 + t) & 31) * 32 + lane);
            float best = 3.4e38f; int bs = 0;
            for (int s = 0; s < ns; ++s) {
                float2 c2 = s_scl[t][s];
                float dr = fi - c2.x, dc = fj - c2.y;
                // match reference: dr*dr + dc*dc (no fma), clamp >= 1
                float d2 = fmaxf(__fadd_rn(__fmul_rn(dr, dr), __fmul_rn(dc, dc)), 1.0f);
                if (d2 < best) { best = d2; bs = s; }
            }
            float w = h[t] * __frsqrt_rn(best);
            int ci = s_sidx[t][bs];
            if (ci != curidx) {
                if (curidx >= 0) {
                    atomicAdd(&s_acc[rep][curidx].x, ax);
                    atomicAdd(&s_acc[rep][curidx].y, ay);
                }
                curidx = ci; ax = 0.f; ay = 0.f;
            }
            ax = __fmaf_rn(fi, w, ax);
            ay = __fmaf_rn(fj, w, ay);
        }
        // warp-uniform final flush
        int  sref = __shfl_sync(full, curidx, 0);
        bool uni  = __all_sync(full, curidx == sref);
        if (uni) {
            #pragma unroll
            for (int o = 16; o; o >>= 1) {
                ax += __shfl_xor_sync(full, ax, o);
                ay += __shfl_xor_sync(full, ay, o);
            }
            if (lane == 0) {
                atomicAdd(&s_acc[rep][sref].x, ax);
                atomicAdd(&s_acc[rep][sref].y, ay);
            }
        } else {
            atomicAdd(&s_acc[rep][curidx].x, ax);
            atomicAdd(&s_acc[rep][curidx].y, ay);
        }
        __syncthreads();

        // ======= write this block's 128 partials (plain stores, no atomics) ==
        if (tid < NC) {
            float x = 0.f, y = 0.f;
            #pragma unroll
            for (int r = 0; r < REPS; ++r) { x += s_acc[r][tid].x; y += s_acc[r][tid].y; }
            g_part2[it & 1][bid][tid] = make_float2(x, y);
        }

        // ================= bare grid barrier (empty critical section) =======
        __syncthreads();
        if (tid == 0) {
            __threadfence();                       // release our partials
            unsigned old = atomicAdd(&g_arrive, 1u);
            if (old == NBLKP - 1) {
                *(volatile unsigned*)&g_arrive = 0u;   // reset for next barrier
                __threadfence();
                atomicAdd(&g_gen, 1u);
            } else if (bid == 0 || it < NITER - 1) {
                // non-zero blocks skip the final poll and just exit
                while ((int)(*(volatile unsigned*)&g_gen - base) < it + 1)
                    __nanosleep(32);
            }
            __threadfence();                       // acquire (invalidates L1D)
        }
        __syncthreads();
    }

    // ================= tail: block 0 reduces the last buffer ================
    if (bid == 0) {
        const int p = (NITER - 1) & 1;
        const int cc = tid & 127, rg = tid >> 7;
        float sx = 0.f, sy = 0.f;
        #pragma unroll
        for (int r = 0; r < 16; ++r) {
            float2 v = g_part2[p][rg + r * 8][cc];
            sx += v.x; sy += v.y;
        }
        s_red[rg][cc] = make_float2(sx, sy);
        __syncthreads();
        if (tid < NC) {
            float x = 0.f, y = 0.f;
            #pragma unroll
            for (int r = 0; r < 8; ++r) { x += s_red[r][tid].x; y += s_red[r][tid].y; }
            out[tid] = make_float2(x, y);
        }
    }
}

extern "C" void kernel_launch(void* const* d_in, const int* in_sizes, int n_in,
                              void* d_out, int out_size)
{
    // Identify inputs by size: clusters = 256 elems, heatmap = 1M.
    const float* clusters = (const float*)d_in[0];
    const float* heat     = (const float*)d_in[1];
    if (in_sizes[0] != NC * 2) {
        clusters = (const float*)d_in[1];
        heat     = (const float*)d_in[0];
    }
    kmeans_persist<<<NBLKP, TPB>>>(clusters, heat, (float2*)d_out);
}